// round 1
// baseline (speedup 1.0000x reference)
#include <cuda_runtime.h>

#define Bq   8
#define Nq   2048
#define DIN  128
#define DOUT 64
#define MT   64
#define NT   64

// Scratch (allocation-free rule: device globals)
__device__ float g_xp[Bq * Nq * DOUT];   // projected features [b][n][d]
__device__ float g_es[Bq * Nq];          // e_src per node
__device__ float g_ed[Bq * Nq];          // e_dst per node

// ---------------------------------------------------------------------------
// Kernel A: xp = x @ W^T + b.  One block = 16 rows; W staged in padded SMEM.
// ---------------------------------------------------------------------------
__global__ __launch_bounds__(256) void k_xproj(const float* __restrict__ x,
                                               const float* __restrict__ W,
                                               const float* __restrict__ bvec) {
    __shared__ float Wsh[DOUT * 132];   // pad 128->132 to break bank conflicts
    __shared__ float xsh[16 * DIN];

    int tid = threadIdx.x;
    for (int i = tid; i < DOUT * DIN; i += 256)
        Wsh[(i >> 7) * 132 + (i & 127)] = W[i];
    int row0 = blockIdx.x * 16;
    for (int i = tid; i < 16 * DIN; i += 256)
        xsh[i] = x[(size_t)row0 * DIN + i];
    __syncthreads();

    int g = tid >> 6;      // group 0..3 (64 threads each)
    int d = tid & 63;      // output feature
    float bb = bvec[d];
    #pragma unroll
    for (int rr = 0; rr < 4; rr++) {
        int rl = g * 4 + rr;
        const float* xr = &xsh[rl * DIN];
        float acc = bb;
        #pragma unroll
        for (int k = 0; k < DIN; k += 4) {
            float4 w4 = *(const float4*)&Wsh[d * 132 + k];
            float4 x4 = *(const float4*)&xr[k];
            acc += x4.x * w4.x;
            acc += x4.y * w4.y;
            acc += x4.z * w4.z;
            acc += x4.w * w4.w;
        }
        g_xp[(size_t)(row0 + rl) * DOUT + d] = acc;
    }
}

// ---------------------------------------------------------------------------
// Kernel A2: es[n] = xp[n]·a_src, ed[n] = xp[n]·a_dst.  One warp per row.
// ---------------------------------------------------------------------------
__global__ __launch_bounds__(256) void k_attvec(const float* __restrict__ a) {
    int tid = threadIdx.x;
    int w = tid >> 5, l = tid & 31;
    int row = blockIdx.x * 8 + w;
    float2 v  = *(const float2*)&g_xp[(size_t)row * DOUT + 2 * l];
    float2 as = *(const float2*)&a[2 * l];
    float2 ad = *(const float2*)&a[DOUT + 2 * l];
    float s = v.x * as.x + v.y * as.y;
    float t = v.x * ad.x + v.y * ad.y;
    #pragma unroll
    for (int off = 16; off; off >>= 1) {
        s += __shfl_xor_sync(0xffffffffu, s, off);
        t += __shfl_xor_sync(0xffffffffu, t, off);
    }
    if (l == 0) { g_es[row] = s; g_ed[row] = t; }
}

// Packed dual-fp32 FMA (Blackwell FFMA2)
__device__ __forceinline__ unsigned long long fma2(unsigned long long a,
                                                   unsigned long long b,
                                                   unsigned long long c) {
    unsigned long long d;
    asm("fma.rn.f32x2 %0, %1, %2, %3;" : "=l"(d) : "l"(a), "l"(b), "l"(c));
    return d;
}

// ---------------------------------------------------------------------------
// Kernel B: fused masked-softmax attention + aggregation.
// Block = (batch b, 64 m-rows). 8 warps, each warp owns 8 m-rows, lane owns a
// d-pair. w tile (64m x 64n) built in SMEM pre-packed as (w,w) float2 so the
// inner loop is LDS.128 broadcast + 2 FFMA2 per (m, 2n).
// ---------------------------------------------------------------------------
__global__ __launch_bounds__(256) void k_gat(const int* __restrict__ adj,
                                             float* __restrict__ out) {
    __shared__ float2 wsh[MT][NT];   // 32 KB

    int tid = threadIdx.x;
    int b  = blockIdx.x >> 5;
    int m0 = (blockIdx.x & 31) * MT;
    int g = tid >> 5, l = tid & 31;

    unsigned long long acc[8];
    float wsum[8];
    #pragma unroll
    for (int j = 0; j < 8; j++) { acc[j] = 0ULL; wsum[j] = 0.f; }

    const float* es  = &g_es[b * Nq];
    const float* ed  = &g_ed[b * Nq];
    const float* xpb = &g_xp[(size_t)b * Nq * DOUT];
    const int* adjb  = adj + (size_t)b * Nq * Nq + (size_t)m0 * Nq;

    int nl4  = (tid & 15) << 2;   // n offset within tile (phase 1)
    int mrow = tid >> 4;          // m offset within tile (phase 1)

    for (int n0 = 0; n0 < Nq; n0 += NT) {
        // ---- phase 1: build w tile (masked leaky-relu exp), packed (w,w) ----
        float4 edv = *(const float4*)&ed[n0 + nl4];
        #pragma unroll
        for (int r = 0; r < 4; r++) {
            int m = mrow + (r << 4);
            float esv = es[m0 + m];
            int4 av = *(const int4*)&adjb[(size_t)m * Nq + n0 + nl4];
            float e0 = esv + edv.x, e1 = esv + edv.y;
            float e2 = esv + edv.z, e3 = esv + edv.w;
            e0 = fmaxf(e0, 0.2f * e0);
            e1 = fmaxf(e1, 0.2f * e1);
            e2 = fmaxf(e2, 0.2f * e2);
            e3 = fmaxf(e3, 0.2f * e3);
            float w0 = av.x ? __expf(e0) : 0.f;
            float w1 = av.y ? __expf(e1) : 0.f;
            float w2 = av.z ? __expf(e2) : 0.f;
            float w3 = av.w ? __expf(e3) : 0.f;
            *(float4*)&wsh[m][nl4]     = make_float4(w0, w0, w1, w1);
            *(float4*)&wsh[m][nl4 + 2] = make_float4(w2, w2, w3, w3);
        }
        __syncthreads();

        // ---- phase 2: acc[m] += w[m][n] * xp[n][dpair], 2 n per step ----
        const float2* xrow = (const float2*)&xpb[(size_t)n0 * DOUT];
        #pragma unroll 4
        for (int nn = 0; nn < NT; nn += 2) {
            unsigned long long x0 = *(const unsigned long long*)&xrow[nn * 32 + l];
            unsigned long long x1 = *(const unsigned long long*)&xrow[nn * 32 + 32 + l];
            #pragma unroll
            for (int j = 0; j < 8; j++) {
                ulonglong2 wq = *(const ulonglong2*)&wsh[g * 8 + j][nn];
                acc[j] = fma2(wq.x, x0, acc[j]);
                acc[j] = fma2(wq.y, x1, acc[j]);
            }
        }

        // ---- per-lane partial denominators from the w tile ----
        #pragma unroll
        for (int j = 0; j < 8; j++) {
            float4 wr = *(const float4*)&wsh[g * 8 + j][2 * l];
            wsum[j] += wr.x + wr.z;
        }
        __syncthreads();
    }

    // reduce denominators across the warp
    #pragma unroll
    for (int j = 0; j < 8; j++) {
        float s = wsum[j];
        #pragma unroll
        for (int off = 16; off; off >>= 1)
            s += __shfl_xor_sync(0xffffffffu, s, off);
        wsum[j] = s;
    }

    // normalize + write
    #pragma unroll
    for (int j = 0; j < 8; j++) {
        int m = m0 + g * 8 + j;
        float inv = 1.0f / wsum[j];
        float ax, ay;
        asm("mov.b64 {%0,%1}, %2;" : "=f"(ax), "=f"(ay) : "l"(acc[j]));
        float2 o;
        o.x = ax * inv;
        o.y = ay * inv;
        *(float2*)&out[((size_t)b * Nq + m) * DOUT + 2 * l] = o;
    }
}

// ---------------------------------------------------------------------------
extern "C" void kernel_launch(void* const* d_in, const int* in_sizes, int n_in,
                              void* d_out, int out_size) {
    const float* x    = (const float*)d_in[0];
    const int*   adj  = (const int*)d_in[1];
    const float* W    = (const float*)d_in[2];
    const float* bvec = (const float*)d_in[3];
    const float* a    = (const float*)d_in[4];
    float* out = (float*)d_out;

    k_xproj<<<Bq * Nq / 16, 256>>>(x, W, bvec);
    k_attvec<<<Bq * Nq / 8, 256>>>(a);
    k_gat<<<Bq * (Nq / MT), 256>>>(adj, out);
}